// round 7
// baseline (speedup 1.0000x reference)
#include <cuda_runtime.h>
#include <cuda_bf16.h>
#include <math.h>

#define BATCH 8
#define SEQ   2048
#define EMB   1024
#define HD    128
#define MROWS (BATCH*SEQ)

// Projected q,k,v as bf16 hi/lo pairs (split once in proj epilogue)
__device__ __align__(16) __nv_bfloat16 g_qh[MROWS*HD];
__device__ __align__(16) __nv_bfloat16 g_ql[MROWS*HD];
__device__ __align__(16) __nv_bfloat16 g_kh[MROWS*HD];
__device__ __align__(16) __nv_bfloat16 g_kl[MROWS*HD];
__device__ __align__(16) __nv_bfloat16 g_vh[MROWS*HD];
__device__ __align__(16) __nv_bfloat16 g_vl[MROWS*HD];

// ---------------------------------------------------------------------------
// helpers
// ---------------------------------------------------------------------------
__device__ __forceinline__ void split2(float x, float y, unsigned& hi, unsigned& lo) {
    asm("cvt.rn.bf16x2.f32 %0, %1, %2;" : "=r"(hi) : "f"(y), "f"(x));
    float rx = x - __uint_as_float(hi << 16);
    float ry = y - __uint_as_float(hi & 0xffff0000u);
    asm("cvt.rn.bf16x2.f32 %0, %1, %2;" : "=r"(lo) : "f"(ry), "f"(rx));
}
__device__ __forceinline__ void store_split4(char* hbase, char* lbase, int off2, float4 v) {
    unsigned h0, l0, h1, l1;
    split2(v.x, v.y, h0, l0);
    split2(v.z, v.w, h1, l1);
    *(uint2*)(hbase + (size_t)off2*2) = make_uint2(h0, h1);
    *(uint2*)(lbase + (size_t)off2*2) = make_uint2(l0, l1);
}
__device__ __forceinline__ void ldsm4(unsigned* r, unsigned addr) {
    asm volatile("ldmatrix.sync.aligned.m8n8.x4.shared.b16 {%0,%1,%2,%3}, [%4];"
        : "=r"(r[0]), "=r"(r[1]), "=r"(r[2]), "=r"(r[3]) : "r"(addr));
}
__device__ __forceinline__ void ldsm4t(unsigned* r, unsigned addr) {
    asm volatile("ldmatrix.sync.aligned.m8n8.x4.trans.shared.b16 {%0,%1,%2,%3}, [%4];"
        : "=r"(r[0]), "=r"(r[1]), "=r"(r[2]), "=r"(r[3]) : "r"(addr));
}
__device__ __forceinline__ void mma_bf16(float* d, const unsigned* a, unsigned b0, unsigned b1) {
    asm volatile("mma.sync.aligned.m16n8k16.row.col.f32.bf16.bf16.f32 "
        "{%0,%1,%2,%3}, {%4,%5,%6,%7}, {%8,%9}, {%0,%1,%2,%3};"
        : "+f"(d[0]), "+f"(d[1]), "+f"(d[2]), "+f"(d[3])
        : "r"(a[0]), "r"(a[1]), "r"(a[2]), "r"(a[3]), "r"(b0), "r"(b1));
}
__device__ __forceinline__ void cp16(unsigned dst, const void* src) {
    asm volatile("cp.async.ca.shared.global [%0], [%1], 16;" :: "r"(dst), "l"(src));
}

// ---------------------------------------------------------------------------
// Kernel 1: QKV projection, bf16 3-product, register-prefetch pipelined.
// Tile 64m x 128n, k-chunk 32, 256 threads (8 warps, 4m x 2n), 2 CTAs/SM.
// ---------------------------------------------------------------------------
#define PJ_XH 0
#define PJ_XL 5120
#define PJ_WH 10240
#define PJ_WL 18944
#define PJ_SMEM 27648

__global__ __launch_bounds__(256, 2) void qkv_proj_bf16(
    const float* __restrict__ x,
    const float* __restrict__ Wk,
    const float* __restrict__ Wq,
    const float* __restrict__ Wv)
{
    extern __shared__ char smraw[];
    const unsigned sb = (unsigned)__cvta_generic_to_shared(smraw);

    const int t = threadIdx.x, lane = t & 31, w = t >> 5;
    const int g = lane >> 2, tg = lane & 3;
    const int wm = w >> 1, wn = w & 1;
    const int rowBase = blockIdx.x * 64;

    const float* W;
    __nv_bfloat16 *oh, *ol;
    if (blockIdx.y == 0)      { W = Wq; oh = g_qh; ol = g_ql; }
    else if (blockIdx.y == 1) { W = Wk; oh = g_kh; ol = g_kl; }
    else                      { W = Wv; oh = g_vh; ol = g_vl; }

    float acc[8][4];
    #pragma unroll
    for (int nb = 0; nb < 8; nb++)
        #pragma unroll
        for (int j = 0; j < 4; j++) acc[nb][j] = 0.f;

    // prefetch registers (chunk 0)
    float4 xr[2], wr[4];
    #pragma unroll
    for (int i = 0; i < 2; i++) {
        int idx = t + i*256;
        int r = idx >> 3, c4 = (idx & 7)*4;
        xr[i] = *(const float4*)(x + (size_t)(rowBase + r)*EMB + c4);
    }
    #pragma unroll
    for (int i = 0; i < 4; i++) {
        int idx = t + i*256;
        int kk = idx >> 5, n4 = (idx & 31)*4;
        wr[i] = *(const float4*)(W + (size_t)kk*HD + n4);
    }

    for (int kc = 0; kc < 32; kc++) {
        // store prefetched chunk (split) into smem
        #pragma unroll
        for (int i = 0; i < 2; i++) {
            int idx = t + i*256;
            int r = idx >> 3, c4 = (idx & 7)*4;
            store_split4(smraw + PJ_XH, smraw + PJ_XL, r*40 + c4, xr[i]);
        }
        #pragma unroll
        for (int i = 0; i < 4; i++) {
            int idx = t + i*256;
            int kk = idx >> 5, n4 = (idx & 31)*4;
            store_split4(smraw + PJ_WH, smraw + PJ_WL, kk*136 + n4, wr[i]);
        }
        __syncthreads();

        // issue next chunk's global loads (in flight during mma)
        if (kc < 31) {
            const int k0 = (kc + 1)*32;
            #pragma unroll
            for (int i = 0; i < 2; i++) {
                int idx = t + i*256;
                int r = idx >> 3, c4 = (idx & 7)*4;
                xr[i] = *(const float4*)(x + (size_t)(rowBase + r)*EMB + k0 + c4);
            }
            #pragma unroll
            for (int i = 0; i < 4; i++) {
                int idx = t + i*256;
                int kk = idx >> 5, n4 = (idx & 31)*4;
                wr[i] = *(const float4*)(W + (size_t)(k0 + kk)*HD + n4);
            }
        }

        #pragma unroll
        for (int ks = 0; ks < 2; ks++) {
            unsigned ah[4], al[4];
            {
                unsigned aoff = ((wm*16 + (lane & 15))*40 + ks*16 + (lane >> 4)*8)*2;
                ldsm4(ah, sb + PJ_XH + aoff);
                ldsm4(al, sb + PJ_XL + aoff);
            }
            unsigned bh[4][4], bl[4][4];
            #pragma unroll
            for (int nb2 = 0; nb2 < 4; nb2++) {
                int krow = ks*16 + (lane & 7) + ((lane >> 3) & 1)*8;
                int ncol = wn*64 + nb2*16 + (lane >> 4)*8;
                unsigned boff = (krow*136 + ncol)*2;
                ldsm4t(bh[nb2], sb + PJ_WH + boff);
                ldsm4t(bl[nb2], sb + PJ_WL + boff);
            }
            #pragma unroll
            for (int nb = 0; nb < 8; nb++) {
                const int nb2 = nb >> 1, h = (nb & 1)*2;
                mma_bf16(acc[nb], ah, bh[nb2][h], bh[nb2][h+1]);
                mma_bf16(acc[nb], ah, bl[nb2][h], bl[nb2][h+1]);
                mma_bf16(acc[nb], al, bh[nb2][h], bh[nb2][h+1]);
            }
        }
        __syncthreads();
    }

    // epilogue: split fp32 acc -> bf16 hi/lo global
    size_t rA = (size_t)(rowBase + wm*16 + g);
    #pragma unroll
    for (int nb = 0; nb < 8; nb++) {
        int col = wn*64 + nb*8 + tg*2;
        unsigned hi, lo;
        split2(acc[nb][0], acc[nb][1], hi, lo);
        *(unsigned*)(oh + rA*HD + col) = hi;
        *(unsigned*)(ol + rA*HD + col) = lo;
        split2(acc[nb][2], acc[nb][3], hi, lo);
        *(unsigned*)(oh + (rA + 8)*HD + col) = hi;
        *(unsigned*)(ol + (rA + 8)*HD + col) = lo;
    }
}

// ---------------------------------------------------------------------------
// Kernel 2: causal flash attention, bf16 3-product mma, cp.async double-buffered.
// BQ = BK = 64, 512 threads (16 warps, 4m x 4n).
// smem layout (bytes):
//   Qh @0  Ql @17408          (64 x 136 elems, 272 B rows)
//   stage s in {0,1} @34816 + s*69632 : Kh +0, Kl +17408, Vh +34816, Vl +52224
//   Ph @174080  Pl @183296    (64 x 72 elems)
//   Mx @192512 (4x64 f32)  Sx @193536 (4x64)  m_s @194560  l_s @194816
// ---------------------------------------------------------------------------
#define AT_QH 0
#define AT_QL 17408
#define AT_STG 34816
#define AT_PH 174080
#define AT_PL 183296
#define AT_MX 192512
#define AT_SX 193536
#define AT_MS 194560
#define AT_LS 194816
#define AT_SMEM 195072

__device__ __forceinline__ void stage_kv(unsigned sb, int stage, int t,
                                         const __nv_bfloat16* kh0, const __nv_bfloat16* kl0,
                                         const __nv_bfloat16* vh0, const __nv_bfloat16* vl0,
                                         int kbase)
{
    const unsigned base = sb + AT_STG + stage*69632;
    #pragma unroll
    for (int i = 0; i < 2; i++) {
        int idx = t + i*512;
        int r = idx >> 4, c8 = idx & 15;
        size_t e = (size_t)(kbase + r)*HD + c8*8;
        unsigned d = base + r*272 + c8*16;
        cp16(d,         kh0 + e);
        cp16(d + 17408, kl0 + e);
        cp16(d + 34816, vh0 + e);
        cp16(d + 52224, vl0 + e);
    }
}

__global__ __launch_bounds__(512) void attn_bf16_kernel(float* __restrict__ out)
{
    extern __shared__ char smraw[];
    const unsigned sb = (unsigned)__cvta_generic_to_shared(smraw);
    float* Mx  = (float*)(smraw + AT_MX);   // [4][64]
    float* Sx  = (float*)(smraw + AT_SX);   // [4][64]
    float* m_s = (float*)(smraw + AT_MS);
    float* l_s = (float*)(smraw + AT_LS);

    const int blk = blockIdx.x;
    const int b   = blk & 7;
    const int qt  = (SEQ/64 - 1) - (blk >> 3);   // heavy tiles first
    const int qbase = qt * 64;

    const int t = threadIdx.x, lane = t & 31, w = t >> 5;
    const int g = lane >> 2, tg = lane & 3;
    const int wm = w >> 2, wn = w & 3;
    const int M0 = wm * 16;

    const size_t boff = (size_t)b*SEQ*HD;
    const __nv_bfloat16 *qh = g_qh + boff, *ql = g_ql + boff;
    const __nv_bfloat16 *kh = g_kh + boff, *kl = g_kl + boff;
    const __nv_bfloat16 *vh = g_vh + boff, *vl = g_vl + boff;

    // stage Q (once) + first K/V stage, one commit group
    #pragma unroll
    for (int i = 0; i < 2; i++) {
        int idx = t + i*512;
        int r = idx >> 4, c8 = idx & 15;
        size_t e = (size_t)(qbase + r)*HD + c8*8;
        cp16(sb + AT_QH + r*272 + c8*16, qh + e);
        cp16(sb + AT_QL + r*272 + c8*16, ql + e);
    }
    stage_kv(sb, 0, t, kh, kl, vh, vl, 0);
    asm volatile("cp.async.commit_group;");

    if (t < 64) { m_s[t] = -1e30f; l_s[t] = 0.f; }

    float o[4][4];
    #pragma unroll
    for (int f = 0; f < 4; f++)
        #pragma unroll
        for (int j = 0; j < 4; j++) o[f][j] = 0.f;

    const float scale = 0.08838834764831845f;  // 128^-0.5

    for (int kt = 0; kt <= qt; kt++) {
        const int kbase = kt * 64;
        const int cur = kt & 1;
        const unsigned stK = sb + AT_STG + cur*69632;
        const unsigned stV = stK + 34816;

        __syncthreads();   // all warps done reading buffer we're about to overwrite
        if (kt < qt) {
            stage_kv(sb, cur ^ 1, t, kh, kl, vh, vl, kbase + 64);
            asm volatile("cp.async.commit_group;");
            asm volatile("cp.async.wait_group 1;");
        } else {
            asm volatile("cp.async.wait_group 0;");
        }
        __syncthreads();   // current buffer visible

        // ---- S = Q K^T : warp m16 x n16 at nb = wn*16 ----
        float s[2][4];
        #pragma unroll
        for (int f = 0; f < 2; f++)
            #pragma unroll
            for (int j = 0; j < 4; j++) s[f][j] = 0.f;

        #pragma unroll
        for (int ks = 0; ks < 8; ks++) {
            unsigned a_h[4], a_l[4];
            {
                unsigned aoff = ((M0 + (lane & 15))*136 + ks*16 + (lane >> 4)*8)*2;
                ldsm4(a_h, sb + AT_QH + aoff);
                ldsm4(a_l, sb + AT_QL + aoff);
            }
            unsigned bh[4], bl[4];
            {
                int nrow = wn*16 + (lane & 7) + (lane >> 4)*8;
                int koff = ks*16 + ((lane >> 3) & 1)*8;
                unsigned bo = (nrow*136 + koff)*2;
                ldsm4(bh, stK + bo);
                ldsm4(bl, stK + 17408 + bo);
            }
            #pragma unroll
            for (int f = 0; f < 2; f++) {
                const int h = f*2;
                mma_bf16(s[f], a_h, bh[h], bh[h+1]);
                mma_bf16(s[f], a_h, bl[h], bl[h+1]);
                mma_bf16(s[f], a_l, bh[h], bh[h+1]);
            }
        }

        // scale + causal mask
        const int rowA = qbase + M0 + g;
        const int rowB = rowA + 8;
        const bool diag = (kt == qt);
        #pragma unroll
        for (int f = 0; f < 2; f++) {
            int c = kbase + wn*16 + f*8 + tg*2;
            s[f][0] *= scale; s[f][1] *= scale; s[f][2] *= scale; s[f][3] *= scale;
            if (diag) {
                if (c     > rowA) s[f][0] = -1e30f;
                if (c + 1 > rowA) s[f][1] = -1e30f;
                if (c     > rowB) s[f][2] = -1e30f;
                if (c + 1 > rowB) s[f][3] = -1e30f;
            }
        }

        // warp-local row max (quad reduce), stash
        float mxA = fmaxf(fmaxf(s[0][0], s[0][1]), fmaxf(s[1][0], s[1][1]));
        float mxB = fmaxf(fmaxf(s[0][2], s[0][3]), fmaxf(s[1][2], s[1][3]));
        mxA = fmaxf(mxA, __shfl_xor_sync(0xffffffffu, mxA, 1));
        mxA = fmaxf(mxA, __shfl_xor_sync(0xffffffffu, mxA, 2));
        mxB = fmaxf(mxB, __shfl_xor_sync(0xffffffffu, mxB, 1));
        mxB = fmaxf(mxB, __shfl_xor_sync(0xffffffffu, mxB, 2));
        const float moldA = m_s[M0 + g];
        const float moldB = m_s[M0 + g + 8];
        if (tg == 0) {
            Mx[wn*64 + M0 + g]     = mxA;
            Mx[wn*64 + M0 + g + 8] = mxB;
        }
        __syncthreads();

        const float mA = fmaxf(fmaxf(moldA, fmaxf(Mx[M0 + g], Mx[64 + M0 + g])),
                               fmaxf(Mx[128 + M0 + g], Mx[192 + M0 + g]));
        const float mB = fmaxf(fmaxf(moldB, fmaxf(Mx[M0 + g + 8], Mx[64 + M0 + g + 8])),
                               fmaxf(Mx[128 + M0 + g + 8], Mx[192 + M0 + g + 8]));
        const float alphaA = __expf(moldA - mA);
        const float alphaB = __expf(moldB - mB);
        if (wn == 0 && tg == 0) {
            m_s[M0 + g]     = mA;
            m_s[M0 + g + 8] = mB;
        }
        float sumA = 0.f, sumB = 0.f;
        #pragma unroll
        for (int f = 0; f < 2; f++) {
            float p0 = __expf(s[f][0] - mA);
            float p1 = __expf(s[f][1] - mA);
            float p2 = __expf(s[f][2] - mB);
            float p3 = __expf(s[f][3] - mB);
            sumA += p0 + p1; sumB += p2 + p3;
            int col = wn*16 + f*8 + tg*2;
            unsigned hi, lo;
            split2(p0, p1, hi, lo);
            *(unsigned*)(smraw + AT_PH + ((M0 + g)*72 + col)*2) = hi;
            *(unsigned*)(smraw + AT_PL + ((M0 + g)*72 + col)*2) = lo;
            split2(p2, p3, hi, lo);
            *(unsigned*)(smraw + AT_PH + ((M0 + g + 8)*72 + col)*2) = hi;
            *(unsigned*)(smraw + AT_PL + ((M0 + g + 8)*72 + col)*2) = lo;
        }
        sumA += __shfl_xor_sync(0xffffffffu, sumA, 1);
        sumA += __shfl_xor_sync(0xffffffffu, sumA, 2);
        sumB += __shfl_xor_sync(0xffffffffu, sumB, 1);
        sumB += __shfl_xor_sync(0xffffffffu, sumB, 2);
        if (tg == 0) {
            Sx[wn*64 + M0 + g]     = sumA;
            Sx[wn*64 + M0 + g + 8] = sumB;
        }
        __syncthreads();

        if (wn == 0 && tg == 0) {
            int r = M0 + g;
            l_s[r] = l_s[r]*alphaA + Sx[r] + Sx[64 + r] + Sx[128 + r] + Sx[192 + r];
            r += 8;
            l_s[r] = l_s[r]*alphaB + Sx[r] + Sx[64 + r] + Sx[128 + r] + Sx[192 + r];
        }

        // rescale O, then O += P V  (warp: m16 x d32 at db = wn*32)
        #pragma unroll
        for (int f = 0; f < 4; f++) {
            o[f][0] *= alphaA; o[f][1] *= alphaA;
            o[f][2] *= alphaB; o[f][3] *= alphaB;
        }
        #pragma unroll
        for (int ks2 = 0; ks2 < 4; ks2++) {
            unsigned a_h[4], a_l[4];
            {
                unsigned aoff = ((M0 + (lane & 15))*72 + ks2*16 + (lane >> 4)*8)*2;
                ldsm4(a_h, sb + AT_PH + aoff);
                ldsm4(a_l, sb + AT_PL + aoff);
            }
            unsigned bh[2][4], bl[2][4];
            #pragma unroll
            for (int db2 = 0; db2 < 2; db2++) {
                int srow = ks2*16 + (lane & 7) + ((lane >> 3) & 1)*8;
                int dcol = wn*32 + db2*16 + (lane >> 4)*8;
                unsigned bo = (srow*136 + dcol)*2;
                ldsm4t(bh[db2], stV + bo);
                ldsm4t(bl[db2], stV + 17408 + bo);
            }
            #pragma unroll
            for (int f = 0; f < 4; f++) {
                const int db2 = f >> 1, h = (f & 1)*2;
                mma_bf16(o[f], a_h, bh[db2][h], bh[db2][h+1]);
                mma_bf16(o[f], a_h, bl[db2][h], bl[db2][h+1]);
                mma_bf16(o[f], a_l, bh[db2][h], bh[db2][h+1]);
            }
        }
    }

    // epilogue
    __syncthreads();
    {
        const float invA = 1.f / l_s[M0 + g];
        const float invB = 1.f / l_s[M0 + g + 8];
        float* Ob = out + ((size_t)b*SEQ + qbase)*HD;
        size_t rA = (size_t)(M0 + g);
        #pragma unroll
        for (int f = 0; f < 4; f++) {
            int col = wn*32 + f*8 + tg*2;
            *(float2*)(Ob + rA*HD + col)       = make_float2(o[f][0]*invA, o[f][1]*invA);
            *(float2*)(Ob + (rA + 8)*HD + col) = make_float2(o[f][2]*invB, o[f][3]*invB);
        }
    }
}

// ---------------------------------------------------------------------------
extern "C" void kernel_launch(void* const* d_in, const int* in_sizes, int n_in,
                              void* d_out, int out_size)
{
    const float* x  = (const float*)d_in[0];
    const float* Wk = (const float*)d_in[1];
    const float* Wq = (const float*)d_in[2];
    const float* Wv = (const float*)d_in[3];
    float* out = (float*)d_out;

    cudaFuncSetAttribute(attn_bf16_kernel,
                         cudaFuncAttributeMaxDynamicSharedMemorySize, AT_SMEM);

    dim3 g1(MROWS/64, 3);
    qkv_proj_bf16<<<g1, 256, PJ_SMEM>>>(x, Wk, Wq, Wv);

    attn_bf16_kernel<<<BATCH*(SEQ/64), 512, AT_SMEM>>>(out);
}

// round 8
// speedup vs baseline: 1.0559x; 1.0559x over previous
#include <cuda_runtime.h>
#include <cuda_bf16.h>
#include <math.h>

#define BATCH 8
#define SEQ   2048
#define EMB   1024
#define HD    128
#define MROWS (BATCH*SEQ)

// Projected q,k,v as bf16 hi/lo pairs (split once in proj epilogue)
__device__ __align__(16) __nv_bfloat16 g_qh[MROWS*HD];
__device__ __align__(16) __nv_bfloat16 g_ql[MROWS*HD];
__device__ __align__(16) __nv_bfloat16 g_kh[MROWS*HD];
__device__ __align__(16) __nv_bfloat16 g_kl[MROWS*HD];
__device__ __align__(16) __nv_bfloat16 g_vh[MROWS*HD];
__device__ __align__(16) __nv_bfloat16 g_vl[MROWS*HD];

// ---------------------------------------------------------------------------
// helpers
// ---------------------------------------------------------------------------
__device__ __forceinline__ void split2(float x, float y, unsigned& hi, unsigned& lo) {
    asm("cvt.rn.bf16x2.f32 %0, %1, %2;" : "=r"(hi) : "f"(y), "f"(x));
    float rx = x - __uint_as_float(hi << 16);
    float ry = y - __uint_as_float(hi & 0xffff0000u);
    asm("cvt.rn.bf16x2.f32 %0, %1, %2;" : "=r"(lo) : "f"(ry), "f"(rx));
}
__device__ __forceinline__ void store_split4(char* hbase, char* lbase, int off2, float4 v) {
    unsigned h0, l0, h1, l1;
    split2(v.x, v.y, h0, l0);
    split2(v.z, v.w, h1, l1);
    *(uint2*)(hbase + (size_t)off2*2) = make_uint2(h0, h1);
    *(uint2*)(lbase + (size_t)off2*2) = make_uint2(l0, l1);
}
__device__ __forceinline__ void ldsm4(unsigned* r, unsigned addr) {
    asm volatile("ldmatrix.sync.aligned.m8n8.x4.shared.b16 {%0,%1,%2,%3}, [%4];"
        : "=r"(r[0]), "=r"(r[1]), "=r"(r[2]), "=r"(r[3]) : "r"(addr));
}
__device__ __forceinline__ void ldsm4t(unsigned* r, unsigned addr) {
    asm volatile("ldmatrix.sync.aligned.m8n8.x4.trans.shared.b16 {%0,%1,%2,%3}, [%4];"
        : "=r"(r[0]), "=r"(r[1]), "=r"(r[2]), "=r"(r[3]) : "r"(addr));
}
__device__ __forceinline__ void mma_bf16(float* d, const unsigned* a, unsigned b0, unsigned b1) {
    asm volatile("mma.sync.aligned.m16n8k16.row.col.f32.bf16.bf16.f32 "
        "{%0,%1,%2,%3}, {%4,%5,%6,%7}, {%8,%9}, {%0,%1,%2,%3};"
        : "+f"(d[0]), "+f"(d[1]), "+f"(d[2]), "+f"(d[3])
        : "r"(a[0]), "r"(a[1]), "r"(a[2]), "r"(a[3]), "r"(b0), "r"(b1));
}
__device__ __forceinline__ void cp16(unsigned dst, const void* src) {
    asm volatile("cp.async.ca.shared.global [%0], [%1], 16;" :: "r"(dst), "l"(src));
}

// ---------------------------------------------------------------------------
// Kernel 1: QKV projection, bf16 3-product, smem double-buffered, 2 CTAs/SM.
// Tile 128m x 64n, k-chunks of 64, 256 threads (8 warps: 4m x 2n, warp m32 x n32).
// grid = (128, 6): blockIdx.y = proj*2 + ntile.
// Buffer (55296 B): Xh[128][72] @0, Xl @18432, Wh[64][72] @36864, Wl @46080.
// ---------------------------------------------------------------------------
#define PJ_XH 0
#define PJ_XL 18432
#define PJ_WH 36864
#define PJ_WL 46080
#define PJ_BUF 55296
#define PJ_SMEM 110592

__global__ __launch_bounds__(256, 2) void qkv_proj_bf16(
    const float* __restrict__ x,
    const float* __restrict__ Wk,
    const float* __restrict__ Wq,
    const float* __restrict__ Wv)
{
    extern __shared__ char smraw[];
    const unsigned sb = (unsigned)__cvta_generic_to_shared(smraw);

    const int t = threadIdx.x, lane = t & 31, w = t >> 5;
    const int g = lane >> 2, tg = lane & 3;
    const int wm = w >> 1, wn = w & 1;
    const int rowBase = blockIdx.x * 128;
    const int proj  = blockIdx.y >> 1;
    const int nBase = (blockIdx.y & 1) * 64;

    const float* W;
    __nv_bfloat16 *oh, *ol;
    if (proj == 0)      { W = Wq; oh = g_qh; ol = g_ql; }
    else if (proj == 1) { W = Wk; oh = g_kh; ol = g_kl; }
    else                { W = Wv; oh = g_vh; ol = g_vl; }

    float acc[2][4][4];
    #pragma unroll
    for (int mf = 0; mf < 2; mf++)
        #pragma unroll
        for (int f = 0; f < 4; f++)
            #pragma unroll
            for (int j = 0; j < 4; j++) acc[mf][f][j] = 0.f;

    // prefetch chunk 0 into registers
    float4 xr[8], wr[4];
    #pragma unroll
    for (int i = 0; i < 8; i++) {
        int idx = t + i*256;
        int r = idx >> 4, c4 = (idx & 15)*4;
        xr[i] = *(const float4*)(x + (size_t)(rowBase + r)*EMB + c4);
    }
    #pragma unroll
    for (int i = 0; i < 4; i++) {
        int idx = t + i*256;
        int kk = idx >> 4, n4 = (idx & 15)*4;
        wr[i] = *(const float4*)(W + (size_t)kk*HD + nBase + n4);
    }

    for (int c = 0; c < 16; c++) {
        char* buf = smraw + (c & 1)*PJ_BUF;
        const unsigned sbb = sb + (c & 1)*PJ_BUF;

        // store prefetched chunk (split) into this buffer
        #pragma unroll
        for (int i = 0; i < 8; i++) {
            int idx = t + i*256;
            int r = idx >> 4, c4 = (idx & 15)*4;
            store_split4(buf + PJ_XH, buf + PJ_XL, r*72 + c4, xr[i]);
        }
        #pragma unroll
        for (int i = 0; i < 4; i++) {
            int idx = t + i*256;
            int kk = idx >> 4, n4 = (idx & 15)*4;
            store_split4(buf + PJ_WH, buf + PJ_WL, kk*72 + n4, wr[i]);
        }
        __syncthreads();   // buffer c&1 ready; prior readers of buffer (c+1)&1 are done

        // issue next chunk's global loads (in flight during mma)
        if (c < 15) {
            const int k0 = (c + 1)*64;
            #pragma unroll
            for (int i = 0; i < 8; i++) {
                int idx = t + i*256;
                int r = idx >> 4, c4 = (idx & 15)*4;
                xr[i] = *(const float4*)(x + (size_t)(rowBase + r)*EMB + k0 + c4);
            }
            #pragma unroll
            for (int i = 0; i < 4; i++) {
                int idx = t + i*256;
                int kk = idx >> 4, n4 = (idx & 15)*4;
                wr[i] = *(const float4*)(W + (size_t)(k0 + kk)*HD + nBase + n4);
            }
        }

        #pragma unroll
        for (int ks = 0; ks < 4; ks++) {
            unsigned ah[2][4], al[2][4];
            #pragma unroll
            for (int mf = 0; mf < 2; mf++) {
                unsigned aoff = ((wm*32 + mf*16 + (lane & 15))*72 + ks*16 + (lane >> 4)*8)*2;
                ldsm4(ah[mf], sbb + PJ_XH + aoff);
                ldsm4(al[mf], sbb + PJ_XL + aoff);
            }
            unsigned bh[2][4], bl[2][4];
            #pragma unroll
            for (int nb2 = 0; nb2 < 2; nb2++) {
                int krow = ks*16 + (lane & 7) + ((lane >> 3) & 1)*8;
                int ncol = wn*32 + nb2*16 + (lane >> 4)*8;
                unsigned boff = (krow*72 + ncol)*2;
                ldsm4t(bh[nb2], sbb + PJ_WH + boff);
                ldsm4t(bl[nb2], sbb + PJ_WL + boff);
            }
            #pragma unroll
            for (int mf = 0; mf < 2; mf++)
                #pragma unroll
                for (int f = 0; f < 4; f++) {
                    const int nb2 = f >> 1, h = (f & 1)*2;
                    mma_bf16(acc[mf][f], ah[mf], bh[nb2][h], bh[nb2][h+1]);
                    mma_bf16(acc[mf][f], ah[mf], bl[nb2][h], bl[nb2][h+1]);
                    mma_bf16(acc[mf][f], al[mf], bh[nb2][h], bh[nb2][h+1]);
                }
        }
        // no second sync: next iter's stores target the other buffer, whose
        // readers (mma of chunk c-1) finished before this iter's sync.
    }

    // epilogue: split fp32 acc -> bf16 hi/lo global
    #pragma unroll
    for (int mf = 0; mf < 2; mf++) {
        size_t rA = (size_t)(rowBase + wm*32 + mf*16 + g);
        #pragma unroll
        for (int f = 0; f < 4; f++) {
            int col = nBase + wn*32 + f*8 + tg*2;
            unsigned hi, lo;
            split2(acc[mf][f][0], acc[mf][f][1], hi, lo);
            *(unsigned*)(oh + rA*HD + col) = hi;
            *(unsigned*)(ol + rA*HD + col) = lo;
            split2(acc[mf][f][2], acc[mf][f][3], hi, lo);
            *(unsigned*)(oh + (rA + 8)*HD + col) = hi;
            *(unsigned*)(ol + (rA + 8)*HD + col) = lo;
        }
    }
}

// ---------------------------------------------------------------------------
// Kernel 2: causal flash attention, bf16 3-product mma, cp.async double-buffered,
// Q fragments hoisted to registers. BQ = BK = 64, 256 threads (8 warps, 4m x 2n).
// smem layout (bytes):
//   Qh @0  Ql @17408          (64 x 136 elems, 272 B rows)
//   stage s in {0,1} @34816 + s*69632 : Kh +0, Kl +17408, Vh +34816, Vl +52224
//   Ph @174080  Pl @183296    (64 x 72 elems)
//   Mx @192512  Sx @193024  m_s @193536  l_s @193792   total 194048
// ---------------------------------------------------------------------------
#define AT_QH 0
#define AT_QL 17408
#define AT_STG 34816
#define AT_PH 174080
#define AT_PL 183296
#define AT_MX 192512
#define AT_SX 193024
#define AT_MS 193536
#define AT_LS 193792
#define AT_SMEM 194048

__device__ __forceinline__ void stage_kv(unsigned sb, int stage, int t,
                                         const __nv_bfloat16* kh0, const __nv_bfloat16* kl0,
                                         const __nv_bfloat16* vh0, const __nv_bfloat16* vl0,
                                         int kbase)
{
    const unsigned base = sb + AT_STG + stage*69632;
    #pragma unroll
    for (int i = 0; i < 4; i++) {
        int idx = t + i*256;
        int r = idx >> 4, c8 = idx & 15;
        size_t e = (size_t)(kbase + r)*HD + c8*8;
        unsigned d = base + r*272 + c8*16;
        cp16(d,         kh0 + e);
        cp16(d + 17408, kl0 + e);
        cp16(d + 34816, vh0 + e);
        cp16(d + 52224, vl0 + e);
    }
}

__global__ __launch_bounds__(256) void attn_bf16_kernel(float* __restrict__ out)
{
    extern __shared__ char smraw[];
    const unsigned sb = (unsigned)__cvta_generic_to_shared(smraw);
    float* Mx  = (float*)(smraw + AT_MX);
    float* Sx  = (float*)(smraw + AT_SX);
    float* m_s = (float*)(smraw + AT_MS);
    float* l_s = (float*)(smraw + AT_LS);

    const int blk = blockIdx.x;
    const int b   = blk & 7;
    const int qt  = (SEQ/64 - 1) - (blk >> 3);   // heavy tiles first
    const int qbase = qt * 64;

    const int t = threadIdx.x, lane = t & 31, w = t >> 5;
    const int g = lane >> 2, tg = lane & 3;
    const int wm = w >> 1, wn = w & 1;
    const int M0 = wm * 16;

    const size_t boff = (size_t)b*SEQ*HD;
    const __nv_bfloat16 *qh = g_qh + boff, *ql = g_ql + boff;
    const __nv_bfloat16 *kh = g_kh + boff, *kl = g_kl + boff;
    const __nv_bfloat16 *vh = g_vh + boff, *vl = g_vl + boff;

    // stage Q (once) + first K/V stage, one commit group; drain it so Q can be
    // hoisted into registers before the mainloop.
    #pragma unroll
    for (int i = 0; i < 4; i++) {
        int idx = t + i*256;
        int r = idx >> 4, c8 = idx & 15;
        size_t e = (size_t)(qbase + r)*HD + c8*8;
        cp16(sb + AT_QH + r*272 + c8*16, qh + e);
        cp16(sb + AT_QL + r*272 + c8*16, ql + e);
    }
    stage_kv(sb, 0, t, kh, kl, vh, vl, 0);
    asm volatile("cp.async.commit_group;");

    if (t < 64) { m_s[t] = -1e30f; l_s[t] = 0.f; }

    asm volatile("cp.async.wait_group 0;");
    __syncthreads();   // Q + stage0 visible to all

    // hoist Q fragments (loop-invariant) into registers
    unsigned qfh[8][4], qfl[8][4];
    #pragma unroll
    for (int ks = 0; ks < 8; ks++) {
        unsigned aoff = ((M0 + (lane & 15))*136 + ks*16 + (lane >> 4)*8)*2;
        ldsm4(qfh[ks], sb + AT_QH + aoff);
        ldsm4(qfl[ks], sb + AT_QL + aoff);
    }

    float o[8][4];
    #pragma unroll
    for (int f = 0; f < 8; f++)
        #pragma unroll
        for (int j = 0; j < 4; j++) o[f][j] = 0.f;

    const float scale = 0.08838834764831845f;  // 128^-0.5

    for (int kt = 0; kt <= qt; kt++) {
        const int kbase = kt * 64;
        const int cur = kt & 1;
        const unsigned stK = sb + AT_STG + cur*69632;
        const unsigned stV = stK + 34816;

        __syncthreads();   // all warps done reading the buffer about to be overwritten
        if (kt < qt) {
            stage_kv(sb, cur ^ 1, t, kh, kl, vh, vl, kbase + 64);
            asm volatile("cp.async.commit_group;");
            asm volatile("cp.async.wait_group 1;");
        } else {
            asm volatile("cp.async.wait_group 0;");
        }
        __syncthreads();   // current buffer visible to all

        // ---- S = Q K^T : warp m16 x n32 ----
        float s[4][4];
        #pragma unroll
        for (int f = 0; f < 4; f++)
            #pragma unroll
            for (int j = 0; j < 4; j++) s[f][j] = 0.f;

        #pragma unroll
        for (int ks = 0; ks < 8; ks++) {
            unsigned bh[2][4], bl[2][4];
            #pragma unroll
            for (int nb2 = 0; nb2 < 2; nb2++) {
                int nrow = wn*32 + nb2*16 + (lane & 7) + (lane >> 4)*8;
                int koff = ks*16 + ((lane >> 3) & 1)*8;
                unsigned bo = (nrow*136 + koff)*2;
                ldsm4(bh[nb2], stK + bo);
                ldsm4(bl[nb2], stK + 17408 + bo);
            }
            #pragma unroll
            for (int f = 0; f < 4; f++) {
                const int nb2 = f >> 1, h = (f & 1)*2;
                mma_bf16(s[f], qfh[ks], bh[nb2][h], bh[nb2][h+1]);
                mma_bf16(s[f], qfh[ks], bl[nb2][h], bl[nb2][h+1]);
                mma_bf16(s[f], qfl[ks], bh[nb2][h], bh[nb2][h+1]);
            }
        }

        // scale + causal mask
        const int rowA = qbase + M0 + g;
        const int rowB = rowA + 8;
        const bool diag = (kt == qt);
        #pragma unroll
        for (int f = 0; f < 4; f++) {
            int c = kbase + wn*32 + f*8 + tg*2;
            s[f][0] *= scale; s[f][1] *= scale; s[f][2] *= scale; s[f][3] *= scale;
            if (diag) {
                if (c     > rowA) s[f][0] = -1e30f;
                if (c + 1 > rowA) s[f][1] = -1e30f;
                if (c     > rowB) s[f][2] = -1e30f;
                if (c + 1 > rowB) s[f][3] = -1e30f;
            }
        }

        // warp-local row max, stash
        float mxA = fmaxf(fmaxf(s[0][0], s[0][1]), fmaxf(s[1][0], s[1][1]));
        mxA = fmaxf(mxA, fmaxf(fmaxf(s[2][0], s[2][1]), fmaxf(s[3][0], s[3][1])));
        float mxB = fmaxf(fmaxf(s[0][2], s[0][3]), fmaxf(s[1][2], s[1][3]));
        mxB = fmaxf(mxB, fmaxf(fmaxf(s[2][2], s[2][3]), fmaxf(s[3][2], s[3][3])));
        mxA = fmaxf(mxA, __shfl_xor_sync(0xffffffffu, mxA, 1));
        mxA = fmaxf(mxA, __shfl_xor_sync(0xffffffffu, mxA, 2));
        mxB = fmaxf(mxB, __shfl_xor_sync(0xffffffffu, mxB, 1));
        mxB = fmaxf(mxB, __shfl_xor_sync(0xffffffffu, mxB, 2));
        const float moldA = m_s[M0 + g];
        const float moldB = m_s[M0 + g + 8];
        if (tg == 0) {
            Mx[wn*64 + M0 + g]     = mxA;
            Mx[wn*64 + M0 + g + 8] = mxB;
        }
        __syncthreads();

        const float mA = fmaxf(moldA, fmaxf(Mx[M0 + g],     Mx[64 + M0 + g]));
        const float mB = fmaxf(moldB, fmaxf(Mx[M0 + g + 8], Mx[64 + M0 + g + 8]));
        const float alphaA = __expf(moldA - mA);
        const float alphaB = __expf(moldB - mB);
        if (wn == 0 && tg == 0) {
            m_s[M0 + g]     = mA;
            m_s[M0 + g + 8] = mB;
        }
        float sumA = 0.f, sumB = 0.f;
        #pragma unroll
        for (int f = 0; f < 4; f++) {
            float p0 = __expf(s[f][0] - mA);
            float p1 = __expf(s[f][1] - mA);
            float p2 = __expf(s[f][2] - mB);
            float p3 = __expf(s[f][3] - mB);
            sumA += p0 + p1; sumB += p2 + p3;
            int col = wn*32 + f*8 + tg*2;
            unsigned hi, lo;
            split2(p0, p1, hi, lo);
            *(unsigned*)(smraw + AT_PH + ((M0 + g)*72 + col)*2) = hi;
            *(unsigned*)(smraw + AT_PL + ((M0 + g)*72 + col)*2) = lo;
            split2(p2, p3, hi, lo);
            *(unsigned*)(smraw + AT_PH + ((M0 + g + 8)*72 + col)*2) = hi;
            *(unsigned*)(smraw + AT_PL + ((M0 + g + 8)*72 + col)*2) = lo;
        }
        sumA += __shfl_xor_sync(0xffffffffu, sumA, 1);
        sumA += __shfl_xor_sync(0xffffffffu, sumA, 2);
        sumB += __shfl_xor_sync(0xffffffffu, sumB, 1);
        sumB += __shfl_xor_sync(0xffffffffu, sumB, 2);
        if (tg == 0) {
            Sx[wn*64 + M0 + g]     = sumA;
            Sx[wn*64 + M0 + g + 8] = sumB;
        }
        __syncthreads();

        if (wn == 0 && tg == 0) {
            int r = M0 + g;
            l_s[r] = l_s[r]*alphaA + Sx[r] + Sx[64 + r];
            r += 8;
            l_s[r] = l_s[r]*alphaB + Sx[r] + Sx[64 + r];
        }

        // rescale O, then O += P V  (warp: m16 x d64)
        #pragma unroll
        for (int f = 0; f < 8; f++) {
            o[f][0] *= alphaA; o[f][1] *= alphaA;
            o[f][2] *= alphaB; o[f][3] *= alphaB;
        }
        #pragma unroll
        for (int ks2 = 0; ks2 < 4; ks2++) {
            unsigned a_h[4], a_l[4];
            {
                unsigned aoff = ((M0 + (lane & 15))*72 + ks2*16 + (lane >> 4)*8)*2;
                ldsm4(a_h, sb + AT_PH + aoff);
                ldsm4(a_l, sb + AT_PL + aoff);
            }
            unsigned bh[2][4], bl[2][4];
            #pragma unroll
            for (int db2 = 0; db2 < 2; db2++) {
                int srow = ks2*16 + (lane & 7) + ((lane >> 3) & 1)*8;
                int dcol = wn*64 + db2*32 + (lane >> 4)*8;
                // d64 slice = 4 x n16 tiles; two pairs below
                unsigned bo = (srow*136 + dcol)*2;
                ldsm4t(bh[db2], stV + bo);
                ldsm4t(bl[db2], stV + 17408 + bo);
            }
            unsigned bh2[2][4], bl2[2][4];
            #pragma unroll
            for (int db2 = 0; db2 < 2; db2++) {
                int srow = ks2*16 + (lane & 7) + ((lane >> 3) & 1)*8;
                int dcol = wn*64 + db2*32 + 16 + (lane >> 4)*8;
                unsigned bo = (srow*136 + dcol)*2;
                ldsm4t(bh2[db2], stV + bo);
                ldsm4t(bl2[db2], stV + 17408 + bo);
            }
            #pragma unroll
            for (int f = 0; f < 8; f++) {
                // f -> d-subtile: f = db2*4 + sub; sub 0,1 from bh, sub 2,3 from bh2
                const int db2 = f >> 2, sub = f & 3;
                const unsigned* BH = (sub < 2) ? bh[db2] : bh2[db2];
                const unsigned* BL = (sub < 2) ? bl[db2] : bl2[db2];
                const int h = (sub & 1)*2;
                mma_bf16(o[f], a_h, BH[h], BH[h+1]);
                mma_bf16(o[f], a_h, BL[h], BL[h+1]);
                mma_bf16(o[f], a_l, BH[h], BH[h+1]);
            }
        }
    }

    // epilogue
    __syncthreads();
    {
        const float invA = 1.f / l_s[M0 + g];
        const float invB = 1.f / l_s[M0 + g + 8];
        float* Ob = out + ((size_t)b*SEQ + qbase)*HD;
        size_t rA = (size_t)(M0 + g);
        #pragma unroll
        for (int f = 0; f < 8; f++) {
            const int db2 = f >> 2, sub = f & 3;
            int col = wn*64 + db2*32 + (sub >> 1)*16 + (sub & 1)*8 + tg*2;
            *(float2*)(Ob + rA*HD + col)       = make_float2(o[f][0]*invA, o[f][1]*invA);
            *(float2*)(Ob + (rA + 8)*HD + col) = make_float2(o[f][2]*invB, o[f][3]*invB);
        }
    }
}

// ---------------------------------------------------------------------------
extern "C" void kernel_launch(void* const* d_in, const int* in_sizes, int n_in,
                              void* d_out, int out_size)
{
    const float* x  = (const float*)d_in[0];
    const float* Wk = (const float*)d_in[1];
    const float* Wq = (const float*)d_in[2];
    const float* Wv = (const float*)d_in[3];
    float* out = (float*)d_out;

    cudaFuncSetAttribute(qkv_proj_bf16,
                         cudaFuncAttributeMaxDynamicSharedMemorySize, PJ_SMEM);
    cudaFuncSetAttribute(attn_bf16_kernel,
                         cudaFuncAttributeMaxDynamicSharedMemorySize, AT_SMEM);

    dim3 g1(MROWS/128, 6);
    qkv_proj_bf16<<<g1, 256, PJ_SMEM>>>(x, Wk, Wq, Wv);

    attn_bf16_kernel<<<BATCH*(SEQ/64), 256, AT_SMEM>>>(out);
}